// round 9
// baseline (speedup 1.0000x reference)
#include <cuda_runtime.h>
#include <cuda_bf16.h>
#include <math.h>

// Problem constants (fixed by setup_inputs)
#define BB      2
#define SEQ     4096
#define DIM     2048
#define NH      16
#define DHALF   64          // Dh/2
#define DHEAD   128
#define NROWS   (BB*SEQ)    // 8192
#define NCHUNK  16
#define CHUNKL  256
#define F3      (3*DIM)     // 6144

// ---------------- scratch (device globals; no allocation allowed) ----------
__device__ float g_xn   [(size_t)NROWS * DIM];   // 64 MB  (normed x)
__device__ float g_xc   [(size_t)NROWS * DIM];   // 64 MB  (conv+silu; later reused for y)
__device__ float g_fused[(size_t)NROWS * F3];    // 192 MB (dt|v|gate -> la|v_in|gate)
__device__ float g_final[(size_t)NROWS * DIM];   // 64 MB  (scan output)
__device__ float g_bd   [BB * NCHUNK * DIM];
__device__ float g_bo   [BB * NCHUNK * DIM];
__device__ float g_carry[BB * NCHUNK * DIM];

// ---------------- packed f32x2 helpers -------------------------------------
__device__ __forceinline__ unsigned long long pack2(float lo, float hi) {
    unsigned long long r;
    asm("mov.b64 %0, {%1,%2};" : "=l"(r) : "f"(lo), "f"(hi));
    return r;
}
__device__ __forceinline__ void fma2(unsigned long long& c,
                                     unsigned long long a, unsigned long long b) {
    asm("fma.rn.f32x2 %0, %1, %2, %0;" : "+l"(c) : "l"(a), "l"(b));
}
__device__ __forceinline__ float2 unpack2(unsigned long long v) {
    float2 f;
    asm("mov.b64 {%0,%1}, %2;" : "=f"(f.x), "=f"(f.y) : "l"(v));
    return f;
}

// ---------------- 1. RMSNorm ------------------------------------------------
__global__ void k_rmsnorm(const float* __restrict__ x,
                          const float* __restrict__ scale) {
    int row = blockIdx.x;
    const float* xr = x + (size_t)row * DIM;
    float*       o  = g_xn + (size_t)row * DIM;

    float s = 0.f;
    for (int i = threadIdx.x; i < DIM; i += blockDim.x) {
        float v = xr[i];
        s += v * v;
    }
    __shared__ float red[32];
    #pragma unroll
    for (int off = 16; off; off >>= 1) s += __shfl_xor_sync(0xffffffffu, s, off);
    if ((threadIdx.x & 31) == 0) red[threadIdx.x >> 5] = s;
    __syncthreads();
    if (threadIdx.x < 32) {
        float t = (threadIdx.x < (blockDim.x >> 5)) ? red[threadIdx.x] : 0.f;
        #pragma unroll
        for (int off = 16; off; off >>= 1) t += __shfl_xor_sync(0xffffffffu, t, off);
        if (threadIdx.x == 0) red[0] = t;
    }
    __syncthreads();
    float rms = rsqrtf(red[0] / (float)DIM + 1e-6f);
    for (int i = threadIdx.x; i < DIM; i += blockDim.x) {
        float v = scale[i] * xr[i] * rms;
        o[i] = fminf(fmaxf(v, -60000.f), 60000.f);
    }
}

// ---------------- 2. depthwise causal conv (K=4) + bias + SiLU -------------
__global__ void k_conv(const float* __restrict__ cw,
                       const float* __restrict__ cb) {
    int idx = blockIdx.x * blockDim.x + threadIdx.x;   // over NROWS*DIM
    if (idx >= NROWS * DIM) return;
    int d   = idx & (DIM - 1);
    int row = idx >> 11;          // /DIM
    int n   = row & (SEQ - 1);

    const float4 w = *reinterpret_cast<const float4*>(&cw[d * 4]);
    float acc = cb[d];
    const float* base = g_xn + (size_t)row * DIM + d;
    // taps: xn[n-3..n] * w[0..3]  (zero pad on the left)
    if (n >= 3) {
        acc += w.x * base[-3 * DIM] + w.y * base[-2 * DIM]
             + w.z * base[-1 * DIM] + w.w * base[0];
    } else {
        if (n >= 3) acc += w.x * base[-3 * DIM];
        if (n >= 2) acc += w.y * base[-2 * DIM];
        if (n >= 1) acc += w.z * base[-1 * DIM];
        acc += w.w * base[0];
    }
    g_xc[idx] = acc / (1.f + expf(-acc));   // silu
}

// ---------------- 3/9. SGEMM: C[M,N] = A[M,K] * B[N,K]^T  (+ residual) -----
// BM=BN=128, BK=16, 256 threads, 8x8 micro-tile via packed f32x2 FMAs.
__global__ __launch_bounds__(256, 2)
void k_gemm(const float* __restrict__ A, const float* __restrict__ Bm,
            float* __restrict__ C, const float* __restrict__ Res,
            int Nn, int Kn) {
    __shared__ __align__(16) float As[16][128];
    __shared__ __align__(16) float Bs[16][128];

    const int tid = threadIdx.x;
    const int tx  = tid & 15;
    const int ty  = tid >> 4;
    const int bx  = blockIdx.x;
    const int by  = blockIdx.y;

    const float* Ab = A  + (size_t)(by * 128) * Kn;
    const float* Bb = Bm + (size_t)(bx * 128) * Kn;

    unsigned long long acc[8][4];
    #pragma unroll
    for (int i = 0; i < 8; i++)
        #pragma unroll
        for (int p = 0; p < 4; p++) acc[i][p] = 0ull;

    for (int kt = 0; kt < Kn; kt += 16) {
        #pragma unroll
        for (int q = 0; q < 2; q++) {
            int l  = tid + q * 256;       // 0..511 float4 slots
            int r  = l >> 2;              // 0..127 tile row
            int c4 = (l & 3) * 4;         // 0,4,8,12
            float4 va = *reinterpret_cast<const float4*>(Ab + (size_t)r * Kn + kt + c4);
            As[c4 + 0][r] = va.x; As[c4 + 1][r] = va.y;
            As[c4 + 2][r] = va.z; As[c4 + 3][r] = va.w;
            float4 vb = *reinterpret_cast<const float4*>(Bb + (size_t)r * Kn + kt + c4);
            Bs[c4 + 0][r] = vb.x; Bs[c4 + 1][r] = vb.y;
            Bs[c4 + 2][r] = vb.z; Bs[c4 + 3][r] = vb.w;
        }
        __syncthreads();

        #pragma unroll
        for (int k = 0; k < 16; k++) {
            float4 a0 = *reinterpret_cast<const float4*>(&As[k][ty * 4]);
            float4 a1 = *reinterpret_cast<const float4*>(&As[k][64 + ty * 4]);
            float4 b0 = *reinterpret_cast<const float4*>(&Bs[k][tx * 4]);
            float4 b1 = *reinterpret_cast<const float4*>(&Bs[k][64 + tx * 4]);

            unsigned long long av[8], bv[4];
            av[0] = pack2(a0.x, a0.x); av[1] = pack2(a0.y, a0.y);
            av[2] = pack2(a0.z, a0.z); av[3] = pack2(a0.w, a0.w);
            av[4] = pack2(a1.x, a1.x); av[5] = pack2(a1.y, a1.y);
            av[6] = pack2(a1.z, a1.z); av[7] = pack2(a1.w, a1.w);
            bv[0] = pack2(b0.x, b0.y); bv[1] = pack2(b0.z, b0.w);
            bv[2] = pack2(b1.x, b1.y); bv[3] = pack2(b1.z, b1.w);

            #pragma unroll
            for (int i = 0; i < 8; i++)
                #pragma unroll
                for (int p = 0; p < 4; p++)
                    fma2(acc[i][p], av[i], bv[p]);
        }
        __syncthreads();
    }

    #pragma unroll
    for (int i = 0; i < 8; i++) {
        int gr = by * 128 + ((i < 4) ? (ty * 4 + i) : (64 + ty * 4 + i - 4));
        float* crow = C + (size_t)gr * Nn + bx * 128;
        const float* rrow = Res ? (Res + (size_t)gr * Nn + bx * 128) : (const float*)0;
        #pragma unroll
        for (int p = 0; p < 4; p++) {
            int col = ((p < 2) ? 0 : 64) + tx * 4 + (p & 1) * 2;
            float2 v = unpack2(acc[i][p]);
            if (Res) {
                float2 r2 = *reinterpret_cast<const float2*>(rrow + col);
                v.x += r2.x; v.y += r2.y;
            }
            *reinterpret_cast<float2*>(crow + col) = v;
        }
    }
}

// ---------------- 4. dt/softplus, RoPE, gate (in place on g_fused) ---------
__global__ void k_post(const float* __restrict__ dt_bias) {
    int idx = blockIdx.x * blockDim.x + threadIdx.x;  // NROWS * NH * 64
    if (idx >= NROWS * NH * DHALF) return;
    int j   = idx & 63;
    int h   = (idx >> 6) & 15;
    int row = idx >> 10;
    int n   = row & (SEQ - 1);

    int d1 = h * DHEAD + j;
    int d2 = d1 + DHALF;
    float* fr = g_fused + (size_t)row * F3;

    // dt = clip(softplus(raw + bias), 0.001, 2)
    float x1 = fr[d1] + dt_bias[d1];
    float x2 = fr[d2] + dt_bias[d2];
    float sp1 = fmaxf(x1, 0.f) + log1pf(expf(-fabsf(x1)));
    float sp2 = fmaxf(x2, 0.f) + log1pf(expf(-fabsf(x2)));
    float dt1 = fminf(fmaxf(sp1, 0.001f), 2.f);
    float dt2 = fminf(fmaxf(sp2, 0.001f), 2.f);
    fr[d1] = -dt1;   // log_alpha
    fr[d2] = -dt2;

    // RoPE
    float invf = powf(10000.0f, -(float)(2 * j) / 128.0f);
    float fr_ang = (float)n * invf;
    float c = cosf(fr_ang), s = sinf(fr_ang);
    float v1 = fr[DIM + d1];
    float v2 = fr[DIM + d2];
    fr[DIM + d1] = (v1 * c - v2 * s) * dt1;   // v_in
    fr[DIM + d2] = (v1 * s + v2 * c) * dt2;

    // gate
    float g1 = fr[2 * DIM + d1];
    float g2 = fr[2 * DIM + d2];
    fr[2 * DIM + d1] = 1.f / (1.f + expf(-g1));
    fr[2 * DIM + d2] = 1.f / (1.f + expf(-g2));
}

// ---------------- 5. within-chunk scan -------------------------------------
__global__ void k_scan() {
    int idx = blockIdx.x * blockDim.x + threadIdx.x;  // BB*NCHUNK*DIM = 65536
    if (idx >= BB * NCHUNK * DIM) return;
    int d  = idx & (DIM - 1);
    int nc = (idx >> 11) & (NCHUNK - 1);
    int b  = idx >> 15;

    size_t rowbase = (size_t)b * SEQ + nc * CHUNKL;
    const float* la = g_fused + rowbase * F3 + d;
    const float* vv = g_fused + rowbase * F3 + DIM + d;
    float*       ot = g_final + rowbase * DIM + d;

    // pass 1: Lmax
    float Ls = 0.f, Lmax = -1e30f;
    for (int i = 0; i < CHUNKL; i++) {
        Ls += la[(size_t)i * F3];
        float L = fminf(fmaxf(Ls, -20.f), 0.f);
        Lmax = fmaxf(Lmax, L);
    }
    // pass 2: stabilized cumulative
    Ls = 0.f;
    float sum = 0.f, lastL = 0.f, lastO = 0.f;
    for (int i = 0; i < CHUNKL; i++) {
        Ls += la[(size_t)i * F3];
        float L  = fminf(fmaxf(Ls, -20.f), 0.f);
        float Lt = L - Lmax;
        sum += expf(-Lt) * vv[(size_t)i * F3];
        float o = expf(Lt) * sum;
        ot[(size_t)i * DIM] = o;
        lastL = L; lastO = o;
    }
    g_bd[idx] = lastL;
    g_bo[idx] = lastO;
}

// ---------------- 6. cross-chunk carry scan --------------------------------
__global__ void k_carry() {
    int idx = blockIdx.x * blockDim.x + threadIdx.x;  // BB*DIM = 4096
    if (idx >= BB * DIM) return;
    int d = idx & (DIM - 1);
    int b = idx >> 11;

    float cd[NCHUNK];
    float run = 0.f, stab = -1e30f;
    #pragma unroll
    for (int nc = 0; nc < NCHUNK; nc++) {
        run += g_bd[(b * NCHUNK + nc) * DIM + d];
        float c = fminf(fmaxf(run, -80.f), 0.f);
        cd[nc] = c;
        stab = fmaxf(stab, c);
    }
    float acc = 0.f;
    #pragma unroll
    for (int nc = 0; nc < NCHUNK; nc++) {
        float ncd = fminf(fmaxf(cd[nc] - stab, -20.f), 0.f);
        g_carry[(b * NCHUNK + nc) * DIM + d] = acc * expf(ncd);
        acc += g_bo[(b * NCHUNK + nc) * DIM + d] * expf(-ncd);
    }
}

// ---------------- 7. apply carries: final += carry * exp(L) ----------------
__global__ void k_final() {
    int idx = blockIdx.x * blockDim.x + threadIdx.x;  // BB*NCHUNK*DIM
    if (idx >= BB * NCHUNK * DIM) return;
    int d  = idx & (DIM - 1);
    int nc = (idx >> 11) & (NCHUNK - 1);
    int b  = idx >> 15;

    float carry = g_carry[idx];
    size_t rowbase = (size_t)b * SEQ + nc * CHUNKL;
    const float* la = g_fused + rowbase * F3 + d;
    float*       ot = g_final + rowbase * DIM + d;

    float Ls = 0.f;
    for (int i = 0; i < CHUNKL; i++) {
        Ls += la[(size_t)i * F3];
        float L = fminf(fmaxf(Ls, -20.f), 0.f);
        ot[(size_t)i * DIM] += carry * expf(L);
    }
}

// ---------------- 8. head mix + gate (y into g_xc) -------------------------
__global__ void k_mix(const float* __restrict__ head_mix) {
    int row = blockIdx.x;
    __shared__ float sf[DIM];
    __shared__ float hm[NH * NH];
    const float* fr = g_final + (size_t)row * DIM;
    const float* gr = g_fused + (size_t)row * F3 + 2 * DIM;
    float*       y  = g_xc + (size_t)row * DIM;

    for (int i = threadIdx.x; i < DIM; i += blockDim.x) sf[i] = fr[i];
    for (int i = threadIdx.x; i < NH * NH; i += blockDim.x) hm[i] = head_mix[i];
    __syncthreads();

    for (int i = threadIdx.x; i < DIM; i += blockDim.x) {
        int dd = i & (DHEAD - 1);
        int m  = i >> 7;
        float acc = 0.f;
        #pragma unroll
        for (int h = 0; h < NH; h++) acc += sf[h * DHEAD + dd] * hm[h * NH + m];
        y[i] = acc * gr[i];
    }
}

// ---------------- launcher --------------------------------------------------
extern "C" void kernel_launch(void* const* d_in, const int* in_sizes, int n_in,
                              void* d_out, int out_size) {
    const float* x          = (const float*)d_in[0];
    const float* norm_scale = (const float*)d_in[1];
    const float* conv_w     = (const float*)d_in[2];
    const float* conv_b     = (const float*)d_in[3];
    const float* in_proj_w  = (const float*)d_in[4];
    const float* dt_bias    = (const float*)d_in[5];
    const float* head_mix   = (const float*)d_in[6];
    const float* out_proj_w = (const float*)d_in[7];
    float* out = (float*)d_out;

    float *p_xc, *p_fused;
    cudaGetSymbolAddress((void**)&p_xc, g_xc);
    cudaGetSymbolAddress((void**)&p_fused, g_fused);

    k_rmsnorm<<<NROWS, 256>>>(x, norm_scale);
    k_conv<<<(NROWS * DIM) / 256, 256>>>(conv_w, conv_b);

    // fused = xc @ in_proj_w^T : M=8192, N=6144, K=2048
    k_gemm<<<dim3(6144 / 128, NROWS / 128), 256>>>(p_xc, in_proj_w, p_fused,
                                                   (const float*)0, 6144, 2048);

    k_post<<<(NROWS * NH * DHALF) / 256, 256>>>(dt_bias);
    k_scan<<<(BB * NCHUNK * DIM) / 256, 256>>>();
    k_carry<<<(BB * DIM) / 256, 256>>>();
    k_final<<<(BB * NCHUNK * DIM) / 256, 256>>>();
    k_mix<<<NROWS, 256>>>(head_mix);

    // out = residual + (vm*gate) @ out_proj_w^T : M=8192, N=2048, K=2048
    k_gemm<<<dim3(2048 / 128, NROWS / 128), 256>>>(p_xc, out_proj_w, out,
                                                   x, 2048, 2048);
}

// round 13
// speedup vs baseline: 1.8686x; 1.8686x over previous
#include <cuda_runtime.h>
#include <cuda_bf16.h>
#include <cstdint>
#include <stdint.h>
#include <math.h>

// Problem constants (fixed by setup_inputs)
#define BB      2
#define SEQ     4096
#define DIM     2048
#define NH      16
#define DHALF   64          // Dh/2
#define DHEAD   128
#define NROWS   (BB*SEQ)    // 8192
#define NCHUNK  16
#define CHUNKL  256
#define F3      (3*DIM)     // 6144

// ---------------- scratch (device globals; no allocation allowed) ----------
__device__ float g_xn   [(size_t)NROWS * DIM];   // normed x
__device__ float g_fused[(size_t)NROWS * F3];    // dt|v|gate -> la|v_in|gate
__device__ float g_final[(size_t)NROWS * DIM];   // scan output
__device__ float g_bd   [BB * NCHUNK * DIM];
__device__ float g_bo   [BB * NCHUNK * DIM];
__device__ float g_carry[BB * NCHUNK * DIM];
// bf16 split operands for tensor-core GEMMs
__device__ __nv_bfloat16 g_a_hi [(size_t)NROWS * DIM];
__device__ __nv_bfloat16 g_a_lo [(size_t)NROWS * DIM];
__device__ __nv_bfloat16 g_b1_hi[(size_t)F3 * DIM];
__device__ __nv_bfloat16 g_b1_lo[(size_t)F3 * DIM];
__device__ __nv_bfloat16 g_b2_hi[(size_t)DIM * DIM];
__device__ __nv_bfloat16 g_b2_lo[(size_t)DIM * DIM];

// ---------------- baseline-ISA tensor-core helpers (sm_80-era, ok on sm_103)
__device__ __forceinline__ uint32_t smem_u32(const void* p) {
    uint32_t a;
    asm("{ .reg .u64 t; cvta.to.shared.u64 t, %1; cvt.u32.u64 %0, t; }"
        : "=r"(a) : "l"(p));
    return a;
}
__device__ __forceinline__ void ldm4(uint32_t* r, uint32_t addr) {
    asm volatile("ldmatrix.sync.aligned.m8n8.x4.shared.b16 {%0,%1,%2,%3}, [%4];"
        : "=r"(r[0]), "=r"(r[1]), "=r"(r[2]), "=r"(r[3]) : "r"(addr));
}
__device__ __forceinline__ void mma_bf16(float* c, const uint32_t* a,
                                         const uint32_t* b) {
    asm volatile(
        "mma.sync.aligned.m16n8k16.row.col.f32.bf16.bf16.f32 "
        "{%0,%1,%2,%3}, {%4,%5,%6,%7}, {%8,%9}, {%0,%1,%2,%3};"
        : "+f"(c[0]), "+f"(c[1]), "+f"(c[2]), "+f"(c[3])
        : "r"(a[0]), "r"(a[1]), "r"(a[2]), "r"(a[3]), "r"(b[0]), "r"(b[1]));
}
__device__ __forceinline__ void cp16(uint32_t sdst, const void* gsrc) {
    asm volatile("cp.async.cg.shared.global [%0], [%1], 16;"
                 :: "r"(sdst), "l"(gsrc));
}
#define CP_COMMIT() asm volatile("cp.async.commit_group;" ::: "memory")
#define CP_WAIT1()  asm volatile("cp.async.wait_group 1;" ::: "memory")
#define CP_WAIT0()  asm volatile("cp.async.wait_group 0;" ::: "memory")

// ---------------- mma.sync GEMM: C[M,N] = A[M,K]*B[N,K]^T (+Res) -----------
// BM=BN=128, BK=32, 8 warps (2m x 4n), warp tile 64x32, bf16 2-split:
// acc += Ah*Bh + Ah*Bl + Al*Bh. 2-stage cp.async pipeline.
// SMEM tile: 128 rows x 32 bf16, row stride 80B (16B-aligned, bank-clean).
#define TILE_B   10240            // 128 * 80
#define STAGE_B  (4 * TILE_B)     // Ah, Al, Bh, Bl
#define SMEM_GEMM (2 * STAGE_B)   // 81920

__global__ __launch_bounds__(256)
void k_gemm_mma(const __nv_bfloat16* __restrict__ Ah, const __nv_bfloat16* __restrict__ Al,
                const __nv_bfloat16* __restrict__ Bh, const __nv_bfloat16* __restrict__ Bl,
                float* __restrict__ C, const float* __restrict__ Res,
                int Nn, int Kn) {
    extern __shared__ char smem[];
    const uint32_t sbase = smem_u32(smem);
    const int tid  = threadIdx.x;
    const int wid  = tid >> 5;
    const int lane = tid & 31;
    const int wm   = wid & 1;        // 2 m-slices of 64
    const int wn   = wid >> 1;       // 4 n-slices of 32
    const int bx = blockIdx.x, by = blockIdx.y;

    const __nv_bfloat16* gp[4];
    gp[0] = Ah + (size_t)(by * 128) * Kn;
    gp[1] = Al + (size_t)(by * 128) * Kn;
    gp[2] = Bh + (size_t)(bx * 128) * Kn;
    gp[3] = Bl + (size_t)(bx * 128) * Kn;

    // per-thread cp.async slots: 2 chunks per tile (512 chunks / 256 thr)
    const int r0 = tid >> 2;                 // rows for q=0 chunk
    const int c0 = tid & 3;                  // 16B sub-chunk
    const int r1 = (tid + 256) >> 2;
    const int c1 = (tid + 256) & 3;

    auto load_stage = [&](int stg, int k0) {
        uint32_t sb = sbase + stg * STAGE_B;
        #pragma unroll
        for (int t = 0; t < 4; t++) {
            cp16(sb + t * TILE_B + r0 * 80 + c0 * 16,
                 gp[t] + (size_t)r0 * Kn + k0 + c0 * 8);
            cp16(sb + t * TILE_B + r1 * 80 + c1 * 16,
                 gp[t] + (size_t)r1 * Kn + k0 + c1 * 8);
        }
        CP_COMMIT();
    };

    float acc[4][4][4];
    #pragma unroll
    for (int mi = 0; mi < 4; mi++)
        #pragma unroll
        for (int ni = 0; ni < 4; ni++)
            #pragma unroll
            for (int k = 0; k < 4; k++) acc[mi][ni][k] = 0.f;

    const int NT = Kn >> 5;          // K tiles of 32
    load_stage(0, 0);

    for (int kt = 0; kt < NT; kt++) {
        const int cur = kt & 1;
        if (kt + 1 < NT) { load_stage(cur ^ 1, (kt + 1) * 32); CP_WAIT1(); }
        else             { CP_WAIT0(); }
        __syncthreads();

        const uint32_t sb = sbase + cur * STAGE_B;
        #pragma unroll
        for (int ks = 0; ks < 2; ks++) {
            const int kc = ks * 16;
            uint32_t a_h[4][4], a_l[4][4], b_h[4][2], b_l[4][2];
            #pragma unroll
            for (int mi = 0; mi < 4; mi++) {
                int arow = wm * 64 + mi * 16 + (lane & 7) + ((lane >> 3) & 1) * 8;
                int acol = kc + ((lane >> 4) & 1) * 8;
                uint32_t ad = sb + arow * 80 + acol * 2;
                ldm4(a_h[mi], ad);
                ldm4(a_l[mi], ad + TILE_B);
            }
            #pragma unroll
            for (int nj = 0; nj < 2; nj++) {
                int brow = wn * 32 + nj * 16 + (lane & 7) + ((lane >> 4) & 1) * 8;
                int bcol = kc + ((lane >> 3) & 1) * 8;
                uint32_t bd = sb + 2 * TILE_B + brow * 80 + bcol * 2;
                uint32_t r[4];
                ldm4(r, bd);
                b_h[nj * 2][0] = r[0]; b_h[nj * 2][1] = r[1];
                b_h[nj * 2 + 1][0] = r[2]; b_h[nj * 2 + 1][1] = r[3];
                ldm4(r, bd + TILE_B);
                b_l[nj * 2][0] = r[0]; b_l[nj * 2][1] = r[1];
                b_l[nj * 2 + 1][0] = r[2]; b_l[nj * 2 + 1][1] = r[3];
            }
            #pragma unroll
            for (int mi = 0; mi < 4; mi++)
                #pragma unroll
                for (int ni = 0; ni < 4; ni++) {
                    mma_bf16(acc[mi][ni], a_h[mi], b_h[ni]);
                    mma_bf16(acc[mi][ni], a_h[mi], b_l[ni]);
                    mma_bf16(acc[mi][ni], a_l[mi], b_h[ni]);
                }
        }
        __syncthreads();
    }

    // epilogue: frag (m16n8) rows g, g+8; cols (lane&3)*2
    #pragma unroll
    for (int mi = 0; mi < 4; mi++) {
        int gr = by * 128 + wm * 64 + mi * 16 + (lane >> 2);
        #pragma unroll
        for (int ni = 0; ni < 4; ni++) {
            int gc = bx * 128 + wn * 32 + ni * 8 + (lane & 3) * 2;
            float2 v0 = make_float2(acc[mi][ni][0], acc[mi][ni][1]);
            float2 v1 = make_float2(acc[mi][ni][2], acc[mi][ni][3]);
            if (Res) {
                float2 q0 = *(const float2*)(Res + (size_t)gr * Nn + gc);
                float2 q1 = *(const float2*)(Res + (size_t)(gr + 8) * Nn + gc);
                v0.x += q0.x; v0.y += q0.y; v1.x += q1.x; v1.y += q1.y;
            }
            *(float2*)(C + (size_t)gr * Nn + gc)       = v0;
            *(float2*)(C + (size_t)(gr + 8) * Nn + gc) = v1;
        }
    }
}

// ---------------- split fp32 -> bf16 hi/lo ---------------------------------
__global__ void k_split(const float* __restrict__ s,
                        __nv_bfloat16* __restrict__ hi,
                        __nv_bfloat16* __restrict__ lo, int n4) {
    int i = blockIdx.x * blockDim.x + threadIdx.x;
    if (i >= n4) return;
    float4 v = ((const float4*)s)[i];
    __nv_bfloat16 h0 = __float2bfloat16(v.x);
    __nv_bfloat16 h1 = __float2bfloat16(v.y);
    __nv_bfloat16 h2 = __float2bfloat16(v.z);
    __nv_bfloat16 h3 = __float2bfloat16(v.w);
    ((__nv_bfloat162*)hi)[2 * i + 0] = __halves2bfloat162(h0, h1);
    ((__nv_bfloat162*)hi)[2 * i + 1] = __halves2bfloat162(h2, h3);
    __nv_bfloat16 l0 = __float2bfloat16(v.x - __bfloat162float(h0));
    __nv_bfloat16 l1 = __float2bfloat16(v.y - __bfloat162float(h1));
    __nv_bfloat16 l2 = __float2bfloat16(v.z - __bfloat162float(h2));
    __nv_bfloat16 l3 = __float2bfloat16(v.w - __bfloat162float(h3));
    ((__nv_bfloat162*)lo)[2 * i + 0] = __halves2bfloat162(l0, l1);
    ((__nv_bfloat162*)lo)[2 * i + 1] = __halves2bfloat162(l2, l3);
}

// ---------------- 1. RMSNorm ------------------------------------------------
__global__ void k_rmsnorm(const float* __restrict__ x,
                          const float* __restrict__ scale) {
    int row = blockIdx.x;
    const float* xr = x + (size_t)row * DIM;
    float*       o  = g_xn + (size_t)row * DIM;

    float s = 0.f;
    for (int i = threadIdx.x; i < DIM; i += blockDim.x) {
        float v = xr[i];
        s += v * v;
    }
    __shared__ float red[32];
    #pragma unroll
    for (int off = 16; off; off >>= 1) s += __shfl_xor_sync(0xffffffffu, s, off);
    if ((threadIdx.x & 31) == 0) red[threadIdx.x >> 5] = s;
    __syncthreads();
    if (threadIdx.x < 32) {
        float t = (threadIdx.x < (blockDim.x >> 5)) ? red[threadIdx.x] : 0.f;
        #pragma unroll
        for (int off = 16; off; off >>= 1) t += __shfl_xor_sync(0xffffffffu, t, off);
        if (threadIdx.x == 0) red[0] = t;
    }
    __syncthreads();
    float rms = rsqrtf(red[0] / (float)DIM + 1e-6f);
    for (int i = threadIdx.x; i < DIM; i += blockDim.x) {
        float v = scale[i] * xr[i] * rms;
        o[i] = fminf(fmaxf(v, -60000.f), 60000.f);
    }
}

// ---------------- 2. depthwise conv + SiLU, emit bf16 hi/lo ----------------
__global__ void k_conv(const float* __restrict__ cw,
                       const float* __restrict__ cb) {
    int idx = blockIdx.x * blockDim.x + threadIdx.x;
    if (idx >= NROWS * DIM) return;
    int d   = idx & (DIM - 1);
    int row = idx >> 11;
    int n   = row & (SEQ - 1);

    const float4 w = *reinterpret_cast<const float4*>(&cw[d * 4]);
    float acc = cb[d];
    const float* base = g_xn + (size_t)row * DIM + d;
    if (n >= 3) {
        acc += w.x * base[-3 * DIM] + w.y * base[-2 * DIM]
             + w.z * base[-1 * DIM] + w.w * base[0];
    } else {
        if (n >= 2) acc += w.y * base[-2 * DIM];
        if (n >= 1) acc += w.z * base[-1 * DIM];
        acc += w.w * base[0];
    }
    float v = acc / (1.f + expf(-acc));
    __nv_bfloat16 h = __float2bfloat16(v);
    g_a_hi[idx] = h;
    g_a_lo[idx] = __float2bfloat16(v - __bfloat162float(h));
}

// ---------------- 4. dt/softplus, RoPE, gate (in place on g_fused) ---------
__global__ void k_post(const float* __restrict__ dt_bias) {
    int idx = blockIdx.x * blockDim.x + threadIdx.x;
    if (idx >= NROWS * NH * DHALF) return;
    int j   = idx & 63;
    int h   = (idx >> 6) & 15;
    int row = idx >> 10;
    int n   = row & (SEQ - 1);

    int d1 = h * DHEAD + j;
    int d2 = d1 + DHALF;
    float* fr = g_fused + (size_t)row * F3;

    float x1 = fr[d1] + dt_bias[d1];
    float x2 = fr[d2] + dt_bias[d2];
    float sp1 = fmaxf(x1, 0.f) + log1pf(expf(-fabsf(x1)));
    float sp2 = fmaxf(x2, 0.f) + log1pf(expf(-fabsf(x2)));
    float dt1 = fminf(fmaxf(sp1, 0.001f), 2.f);
    float dt2 = fminf(fmaxf(sp2, 0.001f), 2.f);
    fr[d1] = -dt1;
    fr[d2] = -dt2;

    float invf = powf(10000.0f, -(float)(2 * j) / 128.0f);
    float ang = (float)n * invf;
    float c = cosf(ang), s = sinf(ang);
    float v1 = fr[DIM + d1];
    float v2 = fr[DIM + d2];
    fr[DIM + d1] = (v1 * c - v2 * s) * dt1;
    fr[DIM + d2] = (v1 * s + v2 * c) * dt2;

    float g1 = fr[2 * DIM + d1];
    float g2 = fr[2 * DIM + d2];
    fr[2 * DIM + d1] = 1.f / (1.f + expf(-g1));
    fr[2 * DIM + d2] = 1.f / (1.f + expf(-g2));
}

// ---------------- 5. within-chunk scan -------------------------------------
__global__ void k_scan() {
    int idx = blockIdx.x * blockDim.x + threadIdx.x;
    if (idx >= BB * NCHUNK * DIM) return;
    int d  = idx & (DIM - 1);
    int nc = (idx >> 11) & (NCHUNK - 1);
    int b  = idx >> 15;

    size_t rowbase = (size_t)b * SEQ + nc * CHUNKL;
    const float* la = g_fused + rowbase * F3 + d;
    const float* vv = g_fused + rowbase * F3 + DIM + d;
    float*       ot = g_final + rowbase * DIM + d;

    float Ls = 0.f, Lmax = -1e30f;
    for (int i = 0; i < CHUNKL; i++) {
        Ls += la[(size_t)i * F3];
        float L = fminf(fmaxf(Ls, -20.f), 0.f);
        Lmax = fmaxf(Lmax, L);
    }
    Ls = 0.f;
    float sum = 0.f, lastL = 0.f, lastO = 0.f;
    for (int i = 0; i < CHUNKL; i++) {
        Ls += la[(size_t)i * F3];
        float L  = fminf(fmaxf(Ls, -20.f), 0.f);
        float Lt = L - Lmax;
        sum += expf(-Lt) * vv[(size_t)i * F3];
        float o = expf(Lt) * sum;
        ot[(size_t)i * DIM] = o;
        lastL = L; lastO = o;
    }
    g_bd[idx] = lastL;
    g_bo[idx] = lastO;
}

// ---------------- 6. cross-chunk carry scan --------------------------------
__global__ void k_carry() {
    int idx = blockIdx.x * blockDim.x + threadIdx.x;
    if (idx >= BB * DIM) return;
    int d = idx & (DIM - 1);
    int b = idx >> 11;

    float cd[NCHUNK];
    float run = 0.f, stab = -1e30f;
    #pragma unroll
    for (int nc = 0; nc < NCHUNK; nc++) {
        run += g_bd[(b * NCHUNK + nc) * DIM + d];
        float c = fminf(fmaxf(run, -80.f), 0.f);
        cd[nc] = c;
        stab = fmaxf(stab, c);
    }
    float acc = 0.f;
    #pragma unroll
    for (int nc = 0; nc < NCHUNK; nc++) {
        float ncd = fminf(fmaxf(cd[nc] - stab, -20.f), 0.f);
        g_carry[(b * NCHUNK + nc) * DIM + d] = acc * expf(ncd);
        acc += g_bo[(b * NCHUNK + nc) * DIM + d] * expf(-ncd);
    }
}

// ---------------- 7. apply carries: final += carry * exp(L) ----------------
__global__ void k_final() {
    int idx = blockIdx.x * blockDim.x + threadIdx.x;
    if (idx >= BB * NCHUNK * DIM) return;
    int d  = idx & (DIM - 1);
    int nc = (idx >> 11) & (NCHUNK - 1);
    int b  = idx >> 15;

    float carry = g_carry[idx];
    size_t rowbase = (size_t)b * SEQ + nc * CHUNKL;
    const float* la = g_fused + rowbase * F3 + d;
    float*       ot = g_final + rowbase * DIM + d;

    float Ls = 0.f;
    for (int i = 0; i < CHUNKL; i++) {
        Ls += la[(size_t)i * F3];
        float L = fminf(fmaxf(Ls, -20.f), 0.f);
        ot[(size_t)i * DIM] += carry * expf(L);
    }
}

// ---------------- 8. head mix + gate, emit bf16 hi/lo ----------------------
__global__ void k_mix(const float* __restrict__ head_mix) {
    int row = blockIdx.x;
    __shared__ float sf[DIM];
    __shared__ float hm[NH * NH];
    const float* fr = g_final + (size_t)row * DIM;
    const float* gr = g_fused + (size_t)row * F3 + 2 * DIM;

    for (int i = threadIdx.x; i < DIM; i += blockDim.x) sf[i] = fr[i];
    for (int i = threadIdx.x; i < NH * NH; i += blockDim.x) hm[i] = head_mix[i];
    __syncthreads();

    for (int i = threadIdx.x; i < DIM; i += blockDim.x) {
        int dd = i & (DHEAD - 1);
        int m  = i >> 7;
        float acc = 0.f;
        #pragma unroll
        for (int h = 0; h < NH; h++) acc += sf[h * DHEAD + dd] * hm[h * NH + m];
        float y = acc * gr[i];
        size_t o = (size_t)row * DIM + i;
        __nv_bfloat16 hv = __float2bfloat16(y);
        g_a_hi[o] = hv;
        g_a_lo[o] = __float2bfloat16(y - __bfloat162float(hv));
    }
}

// ---------------- launcher --------------------------------------------------
extern "C" void kernel_launch(void* const* d_in, const int* in_sizes, int n_in,
                              void* d_out, int out_size) {
    const float* x          = (const float*)d_in[0];
    const float* norm_scale = (const float*)d_in[1];
    const float* conv_w     = (const float*)d_in[2];
    const float* conv_b     = (const float*)d_in[3];
    const float* in_proj_w  = (const float*)d_in[4];
    const float* dt_bias    = (const float*)d_in[5];
    const float* head_mix   = (const float*)d_in[6];
    const float* out_proj_w = (const float*)d_in[7];
    float* out = (float*)d_out;

    float *p_fused;
    __nv_bfloat16 *p_ah, *p_al, *p_b1h, *p_b1l, *p_b2h, *p_b2l;
    cudaGetSymbolAddress((void**)&p_fused, g_fused);
    cudaGetSymbolAddress((void**)&p_ah,  g_a_hi);
    cudaGetSymbolAddress((void**)&p_al,  g_a_lo);
    cudaGetSymbolAddress((void**)&p_b1h, g_b1_hi);
    cudaGetSymbolAddress((void**)&p_b1l, g_b1_lo);
    cudaGetSymbolAddress((void**)&p_b2h, g_b2_hi);
    cudaGetSymbolAddress((void**)&p_b2l, g_b2_lo);

    cudaFuncSetAttribute(k_gemm_mma, cudaFuncAttributeMaxDynamicSharedMemorySize,
                         SMEM_GEMM);

    k_rmsnorm<<<NROWS, 256>>>(x, norm_scale);
    k_conv<<<(NROWS * DIM) / 256, 256>>>(conv_w, conv_b);
    k_split<<<(F3 * DIM / 4) / 256, 256>>>(in_proj_w, p_b1h, p_b1l, F3 * DIM / 4);
    k_split<<<(DIM * DIM / 4) / 256, 256>>>(out_proj_w, p_b2h, p_b2l, DIM * DIM / 4);

    // fused = xc @ in_proj_w^T : M=8192, N=6144, K=2048
    k_gemm_mma<<<dim3(F3 / 128, NROWS / 128), 256, SMEM_GEMM>>>(
        p_ah, p_al, p_b1h, p_b1l, p_fused, (const float*)0, F3, DIM);

    k_post<<<(NROWS * NH * DHALF) / 256, 256>>>(dt_bias);
    k_scan<<<(BB * NCHUNK * DIM) / 256, 256>>>();
    k_carry<<<(BB * DIM + 255) / 256, 256>>>();
    k_final<<<(BB * NCHUNK * DIM) / 256, 256>>>();
    k_mix<<<NROWS, 256>>>(head_mix);

    // out = residual + (vm*gate) @ out_proj_w^T : M=8192, N=2048, K=2048
    k_gemm_mma<<<dim3(DIM / 128, NROWS / 128), 256, SMEM_GEMM>>>(
        p_ah, p_al, p_b2h, p_b2l, out, x, DIM, DIM);
}

// round 14
// speedup vs baseline: 1.9276x; 1.0316x over previous
#include <cuda_runtime.h>
#include <cuda_bf16.h>
#include <cstdint>
#include <stdint.h>
#include <math.h>

// Problem constants (fixed by setup_inputs)
#define BB      2
#define SEQ     4096
#define DIM     2048
#define NH      16
#define DHALF   64          // Dh/2
#define DHEAD   128
#define NROWS   (BB*SEQ)    // 8192
#define NCHUNK  16
#define CHUNKL  256
#define F3      (3*DIM)     // 6144

// ---------------- scratch (device globals; no allocation allowed) ----------
__device__ float g_xn   [(size_t)NROWS * DIM];   // normed x
__device__ float g_fused[(size_t)NROWS * F3];    // dt|v|gate -> la|v_in|gate
__device__ float g_final[(size_t)NROWS * DIM];   // scan output
__device__ float g_bd   [BB * NCHUNK * DIM];
__device__ float g_bo   [BB * NCHUNK * DIM];
__device__ float g_carry[BB * NCHUNK * DIM];
// bf16 split operands for tensor-core GEMMs
__device__ __nv_bfloat16 g_a_hi [(size_t)NROWS * DIM];
__device__ __nv_bfloat16 g_a_lo [(size_t)NROWS * DIM];
__device__ __nv_bfloat16 g_b1_hi[(size_t)F3 * DIM];
__device__ __nv_bfloat16 g_b1_lo[(size_t)F3 * DIM];
__device__ __nv_bfloat16 g_b2_hi[(size_t)DIM * DIM];
__device__ __nv_bfloat16 g_b2_lo[(size_t)DIM * DIM];

// ---------------- baseline-ISA tensor-core helpers (sm_80-era, ok on sm_103)
__device__ __forceinline__ uint32_t smem_u32(const void* p) {
    uint32_t a;
    asm("{ .reg .u64 t; cvta.to.shared.u64 t, %1; cvt.u32.u64 %0, t; }"
        : "=r"(a) : "l"(p));
    return a;
}
__device__ __forceinline__ void ldm4(uint32_t* r, uint32_t addr) {
    asm volatile("ldmatrix.sync.aligned.m8n8.x4.shared.b16 {%0,%1,%2,%3}, [%4];"
        : "=r"(r[0]), "=r"(r[1]), "=r"(r[2]), "=r"(r[3]) : "r"(addr));
}
__device__ __forceinline__ void mma_bf16(float* c, const uint32_t* a,
                                         const uint32_t* b) {
    asm volatile(
        "mma.sync.aligned.m16n8k16.row.col.f32.bf16.bf16.f32 "
        "{%0,%1,%2,%3}, {%4,%5,%6,%7}, {%8,%9}, {%0,%1,%2,%3};"
        : "+f"(c[0]), "+f"(c[1]), "+f"(c[2]), "+f"(c[3])
        : "r"(a[0]), "r"(a[1]), "r"(a[2]), "r"(a[3]), "r"(b[0]), "r"(b[1]));
}
__device__ __forceinline__ void cp16(uint32_t sdst, const void* gsrc) {
    asm volatile("cp.async.cg.shared.global [%0], [%1], 16;"
                 :: "r"(sdst), "l"(gsrc));
}
#define CP_COMMIT() asm volatile("cp.async.commit_group;" ::: "memory")
#define CP_WAIT1()  asm volatile("cp.async.wait_group 1;" ::: "memory")
#define CP_WAIT0()  asm volatile("cp.async.wait_group 0;" ::: "memory")

// ---------------- mma.sync GEMM: C[M,N] = A[M,K]*B[N,K]^T (+Res) -----------
// BM=BN=128, BK=32, 8 warps (2m x 4n), warp tile 64x32, bf16 2-split:
// acc += Ah*Bh + Ah*Bl + Al*Bh. THREE-stage cp.async pipeline, one
// __syncthreads per K-tile (stage kt+2 loads issued right after the sync).
// SMEM tile: 128 rows x 32 bf16, row stride 80B (16B-aligned, bank-clean).
#define TILE_B   10240            // 128 * 80
#define STAGE_B  (4 * TILE_B)     // Ah, Al, Bh, Bl
#define NSTAGE   3
#define SMEM_GEMM (NSTAGE * STAGE_B)   // 122880

__global__ __launch_bounds__(256, 1)
void k_gemm_mma(const __nv_bfloat16* __restrict__ Ah, const __nv_bfloat16* __restrict__ Al,
                const __nv_bfloat16* __restrict__ Bh, const __nv_bfloat16* __restrict__ Bl,
                float* __restrict__ C, const float* __restrict__ Res,
                int Nn, int Kn) {
    extern __shared__ char smem[];
    const uint32_t sbase = smem_u32(smem);
    const int tid  = threadIdx.x;
    const int wid  = tid >> 5;
    const int lane = tid & 31;
    const int wm   = wid & 1;        // 2 m-slices of 64
    const int wn   = wid >> 1;       // 4 n-slices of 32
    const int bx = blockIdx.x, by = blockIdx.y;

    const __nv_bfloat16* gp[4];
    gp[0] = Ah + (size_t)(by * 128) * Kn;
    gp[1] = Al + (size_t)(by * 128) * Kn;
    gp[2] = Bh + (size_t)(bx * 128) * Kn;
    gp[3] = Bl + (size_t)(bx * 128) * Kn;

    // per-thread cp.async slots: 2 chunks per tile (512 chunks / 256 thr)
    const int r0 = tid >> 2;                 // rows for q=0 chunk
    const int c0 = tid & 3;                  // 16B sub-chunk
    const int r1 = (tid + 256) >> 2;
    const int c1 = (tid + 256) & 3;

    auto load_stage = [&](int stg, int k0) {
        uint32_t sb = sbase + stg * STAGE_B;
        #pragma unroll
        for (int t = 0; t < 4; t++) {
            cp16(sb + t * TILE_B + r0 * 80 + c0 * 16,
                 gp[t] + (size_t)r0 * Kn + k0 + c0 * 8);
            cp16(sb + t * TILE_B + r1 * 80 + c1 * 16,
                 gp[t] + (size_t)r1 * Kn + k0 + c1 * 8);
        }
        CP_COMMIT();
    };

    float acc[4][4][4];
    #pragma unroll
    for (int mi = 0; mi < 4; mi++)
        #pragma unroll
        for (int ni = 0; ni < 4; ni++)
            #pragma unroll
            for (int k = 0; k < 4; k++) acc[mi][ni][k] = 0.f;

    const int NT = Kn >> 5;          // K tiles of 32 (>= 2 here)
    load_stage(0, 0);
    load_stage(1, 32);

    for (int kt = 0; kt < NT; kt++) {
        // wait until stage kt's group is complete:
        //  inflight before commit here = {kt, kt+1} (or just {kt} on last iter)
        if (kt + 1 < NT) CP_WAIT1(); else CP_WAIT0();
        __syncthreads();
        // stage (kt+2)%3 was last consumed at iter kt-1; all threads passed
        // the sync above after finishing that compute, so it is free now.
        if (kt + 2 < NT) load_stage((kt + 2) % NSTAGE, (kt + 2) * 32);

        const uint32_t sb = sbase + (kt % NSTAGE) * STAGE_B;
        #pragma unroll
        for (int ks = 0; ks < 2; ks++) {
            const int kc = ks * 16;
            uint32_t a_h[4][4], a_l[4][4], b_h[4][2], b_l[4][2];
            #pragma unroll
            for (int mi = 0; mi < 4; mi++) {
                int arow = wm * 64 + mi * 16 + (lane & 7) + ((lane >> 3) & 1) * 8;
                int acol = kc + ((lane >> 4) & 1) * 8;
                uint32_t ad = sb + arow * 80 + acol * 2;
                ldm4(a_h[mi], ad);
                ldm4(a_l[mi], ad + TILE_B);
            }
            #pragma unroll
            for (int nj = 0; nj < 2; nj++) {
                int brow = wn * 32 + nj * 16 + (lane & 7) + ((lane >> 4) & 1) * 8;
                int bcol = kc + ((lane >> 3) & 1) * 8;
                uint32_t bd = sb + 2 * TILE_B + brow * 80 + bcol * 2;
                uint32_t r[4];
                ldm4(r, bd);
                b_h[nj * 2][0] = r[0]; b_h[nj * 2][1] = r[1];
                b_h[nj * 2 + 1][0] = r[2]; b_h[nj * 2 + 1][1] = r[3];
                ldm4(r, bd + TILE_B);
                b_l[nj * 2][0] = r[0]; b_l[nj * 2][1] = r[1];
                b_l[nj * 2 + 1][0] = r[2]; b_l[nj * 2 + 1][1] = r[3];
            }
            #pragma unroll
            for (int mi = 0; mi < 4; mi++)
                #pragma unroll
                for (int ni = 0; ni < 4; ni++) {
                    mma_bf16(acc[mi][ni], a_h[mi], b_h[ni]);
                    mma_bf16(acc[mi][ni], a_h[mi], b_l[ni]);
                    mma_bf16(acc[mi][ni], a_l[mi], b_h[ni]);
                }
        }
    }
    __syncthreads();

    // epilogue: frag (m16n8) rows g, g+8; cols (lane&3)*2
    #pragma unroll
    for (int mi = 0; mi < 4; mi++) {
        int gr = by * 128 + wm * 64 + mi * 16 + (lane >> 2);
        #pragma unroll
        for (int ni = 0; ni < 4; ni++) {
            int gc = bx * 128 + wn * 32 + ni * 8 + (lane & 3) * 2;
            float2 v0 = make_float2(acc[mi][ni][0], acc[mi][ni][1]);
            float2 v1 = make_float2(acc[mi][ni][2], acc[mi][ni][3]);
            if (Res) {
                float2 q0 = *(const float2*)(Res + (size_t)gr * Nn + gc);
                float2 q1 = *(const float2*)(Res + (size_t)(gr + 8) * Nn + gc);
                v0.x += q0.x; v0.y += q0.y; v1.x += q1.x; v1.y += q1.y;
            }
            *(float2*)(C + (size_t)gr * Nn + gc)       = v0;
            *(float2*)(C + (size_t)(gr + 8) * Nn + gc) = v1;
        }
    }
}

// ---------------- split fp32 -> bf16 hi/lo ---------------------------------
__global__ void k_split(const float* __restrict__ s,
                        __nv_bfloat16* __restrict__ hi,
                        __nv_bfloat16* __restrict__ lo, int n4) {
    int i = blockIdx.x * blockDim.x + threadIdx.x;
    if (i >= n4) return;
    float4 v = ((const float4*)s)[i];
    __nv_bfloat16 h0 = __float2bfloat16(v.x);
    __nv_bfloat16 h1 = __float2bfloat16(v.y);
    __nv_bfloat16 h2 = __float2bfloat16(v.z);
    __nv_bfloat16 h3 = __float2bfloat16(v.w);
    ((__nv_bfloat162*)hi)[2 * i + 0] = __halves2bfloat162(h0, h1);
    ((__nv_bfloat162*)hi)[2 * i + 1] = __halves2bfloat162(h2, h3);
    __nv_bfloat16 l0 = __float2bfloat16(v.x - __bfloat162float(h0));
    __nv_bfloat16 l1 = __float2bfloat16(v.y - __bfloat162float(h1));
    __nv_bfloat16 l2 = __float2bfloat16(v.z - __bfloat162float(h2));
    __nv_bfloat16 l3 = __float2bfloat16(v.w - __bfloat162float(h3));
    ((__nv_bfloat162*)lo)[2 * i + 0] = __halves2bfloat162(l0, l1);
    ((__nv_bfloat162*)lo)[2 * i + 1] = __halves2bfloat162(l2, l3);
}

// ---------------- 1. RMSNorm ------------------------------------------------
__global__ void k_rmsnorm(const float* __restrict__ x,
                          const float* __restrict__ scale) {
    int row = blockIdx.x;
    const float* xr = x + (size_t)row * DIM;
    float*       o  = g_xn + (size_t)row * DIM;

    float s = 0.f;
    for (int i = threadIdx.x; i < DIM; i += blockDim.x) {
        float v = xr[i];
        s += v * v;
    }
    __shared__ float red[32];
    #pragma unroll
    for (int off = 16; off; off >>= 1) s += __shfl_xor_sync(0xffffffffu, s, off);
    if ((threadIdx.x & 31) == 0) red[threadIdx.x >> 5] = s;
    __syncthreads();
    if (threadIdx.x < 32) {
        float t = (threadIdx.x < (blockDim.x >> 5)) ? red[threadIdx.x] : 0.f;
        #pragma unroll
        for (int off = 16; off; off >>= 1) t += __shfl_xor_sync(0xffffffffu, t, off);
        if (threadIdx.x == 0) red[0] = t;
    }
    __syncthreads();
    float rms = rsqrtf(red[0] / (float)DIM + 1e-6f);
    for (int i = threadIdx.x; i < DIM; i += blockDim.x) {
        float v = scale[i] * xr[i] * rms;
        o[i] = fminf(fmaxf(v, -60000.f), 60000.f);
    }
}

// ---------------- 2. depthwise conv + SiLU, emit bf16 hi/lo ----------------
__global__ void k_conv(const float* __restrict__ cw,
                       const float* __restrict__ cb) {
    int idx = blockIdx.x * blockDim.x + threadIdx.x;
    if (idx >= NROWS * DIM) return;
    int d   = idx & (DIM - 1);
    int row = idx >> 11;
    int n   = row & (SEQ - 1);

    const float4 w = *reinterpret_cast<const float4*>(&cw[d * 4]);
    float acc = cb[d];
    const float* base = g_xn + (size_t)row * DIM + d;
    if (n >= 3) {
        acc += w.x * base[-3 * DIM] + w.y * base[-2 * DIM]
             + w.z * base[-1 * DIM] + w.w * base[0];
    } else {
        if (n >= 2) acc += w.y * base[-2 * DIM];
        if (n >= 1) acc += w.z * base[-1 * DIM];
        acc += w.w * base[0];
    }
    float v = acc / (1.f + expf(-acc));
    __nv_bfloat16 h = __float2bfloat16(v);
    g_a_hi[idx] = h;
    g_a_lo[idx] = __float2bfloat16(v - __bfloat162float(h));
}

// ---------------- 4. dt/softplus, RoPE, gate (in place on g_fused) ---------
__global__ void k_post(const float* __restrict__ dt_bias) {
    int idx = blockIdx.x * blockDim.x + threadIdx.x;
    if (idx >= NROWS * NH * DHALF) return;
    int j   = idx & 63;
    int h   = (idx >> 6) & 15;
    int row = idx >> 10;
    int n   = row & (SEQ - 1);

    int d1 = h * DHEAD + j;
    int d2 = d1 + DHALF;
    float* fr = g_fused + (size_t)row * F3;

    float x1 = fr[d1] + dt_bias[d1];
    float x2 = fr[d2] + dt_bias[d2];
    float sp1 = fmaxf(x1, 0.f) + log1pf(expf(-fabsf(x1)));
    float sp2 = fmaxf(x2, 0.f) + log1pf(expf(-fabsf(x2)));
    float dt1 = fminf(fmaxf(sp1, 0.001f), 2.f);
    float dt2 = fminf(fmaxf(sp2, 0.001f), 2.f);
    fr[d1] = -dt1;
    fr[d2] = -dt2;

    float invf = powf(10000.0f, -(float)(2 * j) / 128.0f);
    float ang = (float)n * invf;
    float c = cosf(ang), s = sinf(ang);
    float v1 = fr[DIM + d1];
    float v2 = fr[DIM + d2];
    fr[DIM + d1] = (v1 * c - v2 * s) * dt1;
    fr[DIM + d2] = (v1 * s + v2 * c) * dt2;

    float g1 = fr[2 * DIM + d1];
    float g2 = fr[2 * DIM + d2];
    fr[2 * DIM + d1] = 1.f / (1.f + expf(-g1));
    fr[2 * DIM + d2] = 1.f / (1.f + expf(-g2));
}

// ---------------- 5. within-chunk scan -------------------------------------
__global__ void k_scan() {
    int idx = blockIdx.x * blockDim.x + threadIdx.x;
    if (idx >= BB * NCHUNK * DIM) return;
    int d  = idx & (DIM - 1);
    int nc = (idx >> 11) & (NCHUNK - 1);
    int b  = idx >> 15;

    size_t rowbase = (size_t)b * SEQ + nc * CHUNKL;
    const float* la = g_fused + rowbase * F3 + d;
    const float* vv = g_fused + rowbase * F3 + DIM + d;
    float*       ot = g_final + rowbase * DIM + d;

    float Ls = 0.f, Lmax = -1e30f;
    for (int i = 0; i < CHUNKL; i++) {
        Ls += la[(size_t)i * F3];
        float L = fminf(fmaxf(Ls, -20.f), 0.f);
        Lmax = fmaxf(Lmax, L);
    }
    Ls = 0.f;
    float sum = 0.f, lastL = 0.f, lastO = 0.f;
    for (int i = 0; i < CHUNKL; i++) {
        Ls += la[(size_t)i * F3];
        float L  = fminf(fmaxf(Ls, -20.f), 0.f);
        float Lt = L - Lmax;
        sum += expf(-Lt) * vv[(size_t)i * F3];
        float o = expf(Lt) * sum;
        ot[(size_t)i * DIM] = o;
        lastL = L; lastO = o;
    }
    g_bd[idx] = lastL;
    g_bo[idx] = lastO;
}

// ---------------- 6. cross-chunk carry scan --------------------------------
__global__ void k_carry() {
    int idx = blockIdx.x * blockDim.x + threadIdx.x;
    if (idx >= BB * DIM) return;
    int d = idx & (DIM - 1);
    int b = idx >> 11;

    float cd[NCHUNK];
    float run = 0.f, stab = -1e30f;
    #pragma unroll
    for (int nc = 0; nc < NCHUNK; nc++) {
        run += g_bd[(b * NCHUNK + nc) * DIM + d];
        float c = fminf(fmaxf(run, -80.f), 0.f);
        cd[nc] = c;
        stab = fmaxf(stab, c);
    }
    float acc = 0.f;
    #pragma unroll
    for (int nc = 0; nc < NCHUNK; nc++) {
        float ncd = fminf(fmaxf(cd[nc] - stab, -20.f), 0.f);
        g_carry[(b * NCHUNK + nc) * DIM + d] = acc * expf(ncd);
        acc += g_bo[(b * NCHUNK + nc) * DIM + d] * expf(-ncd);
    }
}

// ---------------- 7. apply carries: final += carry * exp(L) ----------------
__global__ void k_final() {
    int idx = blockIdx.x * blockDim.x + threadIdx.x;
    if (idx >= BB * NCHUNK * DIM) return;
    int d  = idx & (DIM - 1);
    int nc = (idx >> 11) & (NCHUNK - 1);
    int b  = idx >> 15;

    float carry = g_carry[idx];
    size_t rowbase = (size_t)b * SEQ + nc * CHUNKL;
    const float* la = g_fused + rowbase * F3 + d;
    float*       ot = g_final + rowbase * DIM + d;

    float Ls = 0.f;
    for (int i = 0; i < CHUNKL; i++) {
        Ls += la[(size_t)i * F3];
        float L = fminf(fmaxf(Ls, -20.f), 0.f);
        ot[(size_t)i * DIM] += carry * expf(L);
    }
}

// ---------------- 8. head mix + gate, emit bf16 hi/lo ----------------------
__global__ void k_mix(const float* __restrict__ head_mix) {
    int row = blockIdx.x;
    __shared__ float sf[DIM];
    __shared__ float hm[NH * NH];
    const float* fr = g_final + (size_t)row * DIM;
    const float* gr = g_fused + (size_t)row * F3 + 2 * DIM;

    for (int i = threadIdx.x; i < DIM; i += blockDim.x) sf[i] = fr[i];
    for (int i = threadIdx.x; i < NH * NH; i += blockDim.x) hm[i] = head_mix[i];
    __syncthreads();

    for (int i = threadIdx.x; i < DIM; i += blockDim.x) {
        int dd = i & (DHEAD - 1);
        int m  = i >> 7;
        float acc = 0.f;
        #pragma unroll
        for (int h = 0; h < NH; h++) acc += sf[h * DHEAD + dd] * hm[h * NH + m];
        float y = acc * gr[i];
        size_t o = (size_t)row * DIM + i;
        __nv_bfloat16 hv = __float2bfloat16(y);
        g_a_hi[o] = hv;
        g_a_lo[o] = __float2bfloat16(y - __bfloat162float(hv));
    }
}

// ---------------- launcher --------------------------------------------------
extern "C" void kernel_launch(void* const* d_in, const int* in_sizes, int n_in,
                              void* d_out, int out_size) {
    const float* x          = (const float*)d_in[0];
    const float* norm_scale = (const float*)d_in[1];
    const float* conv_w     = (const float*)d_in[2];
    const float* conv_b     = (const float*)d_in[3];
    const float* in_proj_w  = (const float*)d_in[4];
    const float* dt_bias    = (const float*)d_in[5];
    const float* head_mix   = (const float*)d_in[6];
    const float* out_proj_w = (const float*)d_in[7];
    float* out = (float*)d_out;

    float *p_fused;
    __nv_bfloat16 *p_ah, *p_al, *p_b1h, *p_b1l, *p_b2h, *p_b2l;
    cudaGetSymbolAddress((void**)&p_fused, g_fused);
    cudaGetSymbolAddress((void**)&p_ah,  g_a_hi);
    cudaGetSymbolAddress((void**)&p_al,  g_a_lo);
    cudaGetSymbolAddress((void**)&p_b1h, g_b1_hi);
    cudaGetSymbolAddress((void**)&p_b1l, g_b1_lo);
    cudaGetSymbolAddress((void**)&p_b2h, g_b2_hi);
    cudaGetSymbolAddress((void**)&p_b2l, g_b2_lo);

    cudaFuncSetAttribute(k_gemm_mma, cudaFuncAttributeMaxDynamicSharedMemorySize,
                         SMEM_GEMM);

    k_rmsnorm<<<NROWS, 256>>>(x, norm_scale);
    k_conv<<<(NROWS * DIM) / 256, 256>>>(conv_w, conv_b);
    k_split<<<(F3 * DIM / 4) / 256, 256>>>(in_proj_w, p_b1h, p_b1l, F3 * DIM / 4);
    k_split<<<(DIM * DIM / 4) / 256, 256>>>(out_proj_w, p_b2h, p_b2l, DIM * DIM / 4);

    // fused = xc @ in_proj_w^T : M=8192, N=6144, K=2048
    k_gemm_mma<<<dim3(F3 / 128, NROWS / 128), 256, SMEM_GEMM>>>(
        p_ah, p_al, p_b1h, p_b1l, p_fused, (const float*)0, F3, DIM);

    k_post<<<(NROWS * NH * DHALF) / 256, 256>>>(dt_bias);
    k_scan<<<(BB * NCHUNK * DIM) / 256, 256>>>();
    k_carry<<<(BB * DIM + 255) / 256, 256>>>();
    k_final<<<(BB * NCHUNK * DIM) / 256, 256>>>();
    k_mix<<<NROWS, 256>>>(head_mix);

    // out = residual + (vm*gate) @ out_proj_w^T : M=8192, N=2048, K=2048
    k_gemm_mma<<<dim3(DIM / 128, NROWS / 128), 256, SMEM_GEMM>>>(
        p_ah, p_al, p_b2h, p_b2l, out, x, DIM, DIM);
}